// round 5
// baseline (speedup 1.0000x reference)
#include <cuda_runtime.h>
#include <cuda_bf16.h>
#include <cstdint>

// ---------------- configuration ----------------
#define NB      4            // batches per CTA
#define THREADS 256
#define HPAD    65           // h row pitch (floats)
#define NT0     16           // layer-0 K tiles (K=1024, 64 k per tile)
#define NT_ALL  48           // + 32 layer-1 tiles (K=2048)
#define NITER   192          // NT_ALL * NB
#define WPITCH  144          // W/z row pitch in bytes (72 bf16)
#define WPLANE  18432        // 128 rows * 144B  (one bf16 plane of a W tile)
#define WTILE   36864        // hi+lo planes
#define ZPLANE  9216         // 64 rows * 144B
#define ZTILE   18432        // hi+lo planes

// dynamic smem byte offsets
#define OFF_X   0            // 4 * 8192   x fp32 [32][64] per batch
#define OFF_H   32768        // 4 * 16640  h fp32 [64][HPAD] per batch
#define OFF_W   99328        // 2 * WTILE
#define OFF_Z   173056       // 2 * ZTILE   (epilogue partial sums overlay here)
#define SMEM_TOTAL 209920

// pre-split W: 48 tiles, each [hi plane 128x144B][lo plane 128x144B]
__device__ __align__(16) unsigned char g_Wpre[48 * WTILE];

// ---------------- helpers ----------------
static __device__ __forceinline__ uint32_t smem_u32(const void* p) {
    return (uint32_t)__cvta_generic_to_shared(p);
}
static __device__ __forceinline__ void cpa16(uint32_t dst, const void* src) {
    asm volatile("cp.async.cg.shared.global [%0], [%1], 16;" :: "r"(dst), "l"(src));
}
static __device__ __forceinline__ void cp_commit() { asm volatile("cp.async.commit_group;"); }
template <int N>
static __device__ __forceinline__ void cp_wait() { asm volatile("cp.async.wait_group %0;" :: "n"(N)); }

static __device__ __forceinline__ void sts128(uint32_t a, uint32_t r0, uint32_t r1, uint32_t r2, uint32_t r3) {
    asm volatile("st.shared.v4.b32 [%0], {%1, %2, %3, %4};" :: "r"(a), "r"(r0), "r"(r1), "r"(r2), "r"(r3));
}
// 4x m8n8 b16 matrices; volatile => ordered w.r.t. barriers & sts (both volatile)
static __device__ __forceinline__ void ldmx4(uint32_t* r, uint32_t a) {
    asm volatile("ldmatrix.sync.aligned.m8n8.x4.shared.b16 {%0,%1,%2,%3}, [%4];"
        : "=r"(r[0]), "=r"(r[1]), "=r"(r[2]), "=r"(r[3]) : "r"(a));
}
// m16n8k16 row.col bf16 -> f32, D += A*B (register-pure; NON-volatile so the
// scheduler can interleave z-build FMA/CVT work under MMA issue)
static __device__ __forceinline__ void mma16816(float* c, const uint32_t* a, const uint32_t* b) {
    asm("mma.sync.aligned.m16n8k16.row.col.f32.bf16.bf16.f32 "
        "{%0,%1,%2,%3}, {%4,%5,%6,%7}, {%8,%9}, {%0,%1,%2,%3};"
        : "+f"(c[0]), "+f"(c[1]), "+f"(c[2]), "+f"(c[3])
        : "r"(a[0]), "r"(a[1]), "r"(a[2]), "r"(a[3]), "r"(b[0]), "r"(b[1]));
}

// ---------------- prep: split W into bf16 hi/lo, padded-pitch tiles ----------------
__global__ void prep_kernel(const float* __restrict__ W0, const float* __restrict__ W1) {
    int idx = blockIdx.x * 256 + threadIdx.x;      // 0..393215
    float w; int o, k; size_t base;
    if (idx < 131072) { o = idx >> 10; k = idx & 1023; w = W0[idx]; base = (size_t)(k >> 6) * WTILE; }
    else { int j = idx - 131072; o = j >> 11; k = j & 2047; w = W1[j]; base = 16 * WTILE + (size_t)(k >> 6) * WTILE; }
    __nv_bfloat16 hi = __float2bfloat16(w);
    __nv_bfloat16 lo = __float2bfloat16(w - __bfloat162float(hi));
    int c = k & 63;
    size_t off = base + (size_t)o * WPITCH + (size_t)c * 2;
    *(__nv_bfloat16*)(g_Wpre + off)          = hi;
    *(__nv_bfloat16*)(g_Wpre + off + WPLANE) = lo;
}

// ---------------- main kernel ----------------
__global__ __launch_bounds__(THREADS, 1)
void cin_mma_kernel(const float* __restrict__ xg,
                    const float* __restrict__ b0g,
                    const float* __restrict__ b1g,
                    float* __restrict__ out)
{
    extern __shared__ __align__(256) unsigned char smem[];
    const uint32_t sb = smem_u32(smem);
    const int tid  = threadIdx.x;
    const int wid  = tid >> 5;
    const int lane = tid & 31;
    const int lr   = lane >> 2;     // fragment row within 8
    const int lc   = lane & 3;      // fragment col group

    const int wo = wid >> 1;        // warp o-tile (0..3) -> o base wo*32
    const int wn = wid & 1;         // warp n-tile (0..1) -> d base wn*32

    // ldmatrix per-lane address offsets (derived from verified R4 manual maps)
    const uint32_t aOff = (uint32_t)((lane & 15) * WPITCH + ((lane & 16) ? 16 : 0));
    const uint32_t bOff = (uint32_t)(((lane & 7) + ((lane & 16) >> 1)) * WPITCH + ((lane & 8) << 1));

    float* xs = (float*)(smem + OFF_X);
    float* hs = (float*)(smem + OFF_H);

    const int bbase = blockIdx.x * NB;

    // initial loads: x (32KB) + W tile 0, one cp.async group
    {
        const char* src = (const char*)(xg + (size_t)bbase * 2048);
        #pragma unroll
        for (int r = 0; r < 8; r++)
            cpa16(sb + OFF_X + (uint32_t)(r * THREADS + tid) * 16, src + (size_t)(r * THREADS + tid) * 16);
        #pragma unroll
        for (int r = 0; r < 9; r++) {
            int idx = r * THREADS + tid;
            if (idx < WTILE / 16)
                cpa16(sb + OFF_W + (uint32_t)idx * 16, g_Wpre + (size_t)idx * 16);
        }
        cp_commit();
    }

    // z producer mapping
    const int d  = tid & 63;
    const int kq = tid >> 6;        // 0..3 -> 16-k strip
    const int kb = kq * 16;
    const int m0 = (kq & 1) * 16;

    // build z tile for flat iter j into buffer (j&1)
    auto build_z = [&](int j) {
        int g = j >> 2, b = j & 3;
        int gl = (g < NT0) ? g : g - NT0;
        int hid = gl * 2 + (kq >> 1);
        const uint32_t zbuf = sb + OFF_Z + (uint32_t)(j & 1) * ZTILE;
        const float* xb = xs + (size_t)b * 2048;
        const float* hrow = (g < NT0) ? (xb + hid * 64)
                                      : (hs + (size_t)b * (64 * HPAD) + hid * HPAD);
        const float xh = hrow[d];
        uint32_t hi[8], lo[8];
        #pragma unroll
        for (int i = 0; i < 8; i++) {
            float z0 = xh * xb[(m0 + 2 * i) * 64 + d];
            float z1 = xh * xb[(m0 + 2 * i + 1) * 64 + d];
            uint32_t p0; asm("cvt.rn.bf16x2.f32 %0, %1, %2;" : "=r"(p0) : "f"(z1), "f"(z0));
            float r0 = z0 - __uint_as_float(p0 << 16);
            float r1 = z1 - __uint_as_float(p0 & 0xFFFF0000u);
            uint32_t p1; asm("cvt.rn.bf16x2.f32 %0, %1, %2;" : "=r"(p1) : "f"(r1), "f"(r0));
            hi[i] = p0; lo[i] = p1;
        }
        uint32_t a0 = zbuf + (uint32_t)(d * WPITCH + kb * 2);
        sts128(a0,               hi[0], hi[1], hi[2], hi[3]);
        sts128(a0 + 16,          hi[4], hi[5], hi[6], hi[7]);
        sts128(a0 + ZPLANE,      lo[0], lo[1], lo[2], lo[3]);
        sts128(a0 + ZPLANE + 16, lo[4], lo[5], lo[6], lo[7]);
    };

    float acc[NB][2][4][4];
    #pragma unroll
    for (int b = 0; b < NB; b++)
        #pragma unroll
        for (int mi = 0; mi < 2; mi++)
            #pragma unroll
            for (int nj = 0; nj < 4; nj++)
                #pragma unroll
                for (int q = 0; q < 4; q++) acc[b][mi][nj][q] = 0.0f;

    cp_wait<0>();          // x + W0 resident
    __syncthreads();
    build_z(0);

    for (int i = 0; i < NITER; i++) {
        const int g = i >> 2, b = i & 3;
        if (b == 0 && g > 0) cp_wait<0>();   // W(g) resident (prefetched at g-1)
        __syncthreads();                      // z(i) visible; z(i-1) readers done

        // pipeline: build z(i+1) first (FMA/CVT work overlaps MMA issue below)
        if (i + 1 < NITER && i != 63) build_z(i + 1);

        if (b == 0 && g + 1 < NT_ALL) {       // prefetch next W tile
            const unsigned char* src = g_Wpre + (size_t)(g + 1) * WTILE;
            uint32_t dst = sb + OFF_W + (uint32_t)((g + 1) & 1) * WTILE;
            #pragma unroll
            for (int r = 0; r < 9; r++) {
                int idx = r * THREADS + tid;
                if (idx < WTILE / 16)
                    cpa16(dst + (uint32_t)idx * 16, src + (size_t)idx * 16);
            }
            cp_commit();
        }

        // ---- MMA block for iter i
        {
            const uint32_t wtile = sb + OFF_W + (uint32_t)(g & 1) * WTILE;
            const uint32_t zbuf  = sb + OFF_Z + (uint32_t)(i & 1) * ZTILE;
            const uint32_t aBase = wtile + (uint32_t)(wo * 32 * WPITCH) + aOff;
            const uint32_t bBase = zbuf + (uint32_t)(wn * 32 * WPITCH) + bOff;
            #pragma unroll
            for (int ks = 0; ks < 4; ks++) {
                uint32_t Ah0[4], Ah1[4], Al0[4], Al1[4];
                uint32_t Bh01[4], Bh23[4], Bl01[4], Bl23[4];
                const uint32_t ab = aBase + (uint32_t)(ks * 32);
                const uint32_t bb = bBase + (uint32_t)(ks * 32);
                ldmx4(Ah0, ab);
                ldmx4(Ah1, ab + 16 * WPITCH);
                ldmx4(Al0, ab + WPLANE);
                ldmx4(Al1, ab + WPLANE + 16 * WPITCH);
                ldmx4(Bh01, bb);
                ldmx4(Bh23, bb + 16 * WPITCH);
                ldmx4(Bl01, bb + ZPLANE);
                ldmx4(Bl23, bb + ZPLANE + 16 * WPITCH);
                // pass 1: Ahi * Bhi
                mma16816(acc[b][0][0], Ah0, Bh01);     mma16816(acc[b][0][1], Ah0, Bh01 + 2);
                mma16816(acc[b][0][2], Ah0, Bh23);     mma16816(acc[b][0][3], Ah0, Bh23 + 2);
                mma16816(acc[b][1][0], Ah1, Bh01);     mma16816(acc[b][1][1], Ah1, Bh01 + 2);
                mma16816(acc[b][1][2], Ah1, Bh23);     mma16816(acc[b][1][3], Ah1, Bh23 + 2);
                // pass 2: Ahi * Blo
                mma16816(acc[b][0][0], Ah0, Bl01);     mma16816(acc[b][0][1], Ah0, Bl01 + 2);
                mma16816(acc[b][0][2], Ah0, Bl23);     mma16816(acc[b][0][3], Ah0, Bl23 + 2);
                mma16816(acc[b][1][0], Ah1, Bl01);     mma16816(acc[b][1][1], Ah1, Bl01 + 2);
                mma16816(acc[b][1][2], Ah1, Bl23);     mma16816(acc[b][1][3], Ah1, Bl23 + 2);
                // pass 3: Alo * Bhi
                mma16816(acc[b][0][0], Al0, Bh01);     mma16816(acc[b][0][1], Al0, Bh01 + 2);
                mma16816(acc[b][0][2], Al0, Bh23);     mma16816(acc[b][0][3], Al0, Bh23 + 2);
                mma16816(acc[b][1][0], Al1, Bh01);     mma16816(acc[b][1][1], Al1, Bh01 + 2);
                mma16816(acc[b][1][2], Al1, Bh23);     mma16816(acc[b][1][3], Al1, Bh23 + 2);
            }
        }

        if (i == 63) {
            // ======== layer-0 epilogue ========
            __syncthreads();                        // all iter-63 smem reads done
            float* ps = (float*)(smem + OFF_Z);     // partial sums overlay (buf0)
            #pragma unroll
            for (int bb = 0; bb < NB; bb++) {
                #pragma unroll
                for (int mi = 0; mi < 2; mi++) {
                    int o  = wo * 32 + mi * 16 + lr;
                    float bias0 = b0g[o], bias1 = b0g[o + 8];
                    if (wo < 2) {
                        float* h0 = hs + (size_t)bb * (64 * HPAD) + o * HPAD;
                        float* h1 = h0 + 8 * HPAD;
                        #pragma unroll
                        for (int nj = 0; nj < 4; nj++) {
                            int dd = wn * 32 + nj * 8 + 2 * lc;
                            h0[dd]     = fmaxf(acc[bb][mi][nj][0] + bias0, 0.0f);
                            h0[dd + 1] = fmaxf(acc[bb][mi][nj][1] + bias0, 0.0f);
                            h1[dd]     = fmaxf(acc[bb][mi][nj][2] + bias1, 0.0f);
                            h1[dd + 1] = fmaxf(acc[bb][mi][nj][3] + bias1, 0.0f);
                        }
                    } else {
                        float s0 = 0.0f, s1 = 0.0f;
                        #pragma unroll
                        for (int nj = 0; nj < 4; nj++) {
                            s0 += fmaxf(acc[bb][mi][nj][0] + bias0, 0.0f)
                                + fmaxf(acc[bb][mi][nj][1] + bias0, 0.0f);
                            s1 += fmaxf(acc[bb][mi][nj][2] + bias1, 0.0f)
                                + fmaxf(acc[bb][mi][nj][3] + bias1, 0.0f);
                        }
                        s0 += __shfl_xor_sync(0xffffffffu, s0, 1);
                        s0 += __shfl_xor_sync(0xffffffffu, s0, 2);
                        s1 += __shfl_xor_sync(0xffffffffu, s1, 1);
                        s1 += __shfl_xor_sync(0xffffffffu, s1, 2);
                        if (lc == 0) {
                            int row = (wo - 2) * 32 + mi * 16 + lr;
                            ps[wn * 256 + bb * 64 + row]     = s0;
                            ps[wn * 256 + bb * 64 + row + 8] = s1;
                        }
                    }
                }
            }
            __syncthreads();
            {
                int bb = tid >> 6, row = tid & 63;
                out[(size_t)(bbase + bb) * 192 + row] = ps[bb * 64 + row] + ps[256 + bb * 64 + row];
            }
            // reset accumulators for layer 1
            #pragma unroll
            for (int bb = 0; bb < NB; bb++)
                #pragma unroll
                for (int mi = 0; mi < 2; mi++)
                    #pragma unroll
                    for (int nj = 0; nj < 4; nj++)
                        #pragma unroll
                        for (int q = 0; q < 4; q++) acc[bb][mi][nj][q] = 0.0f;
            __syncthreads();      // ps reads done before z(64) overwrites buf0
            build_z(64);          // uses hs written above
        }
    }

    // ======== layer-1 epilogue: out rows 64..191 ========
    __syncthreads();
    {
        float* ps = (float*)(smem + OFF_Z);   // [wn][b][row<128]
        #pragma unroll
        for (int b = 0; b < NB; b++) {
            #pragma unroll
            for (int mi = 0; mi < 2; mi++) {
                int o = wo * 32 + mi * 16 + lr;
                float bias0 = b1g[o], bias1 = b1g[o + 8];
                float s0 = 0.0f, s1 = 0.0f;
                #pragma unroll
                for (int nj = 0; nj < 4; nj++) {
                    s0 += fmaxf(acc[b][mi][nj][0] + bias0, 0.0f)
                        + fmaxf(acc[b][mi][nj][1] + bias0, 0.0f);
                    s1 += fmaxf(acc[b][mi][nj][2] + bias1, 0.0f)
                        + fmaxf(acc[b][mi][nj][3] + bias1, 0.0f);
                }
                s0 += __shfl_xor_sync(0xffffffffu, s0, 1);
                s0 += __shfl_xor_sync(0xffffffffu, s0, 2);
                s1 += __shfl_xor_sync(0xffffffffu, s1, 1);
                s1 += __shfl_xor_sync(0xffffffffu, s1, 2);
                if (lc == 0) {
                    ps[wn * 512 + b * 128 + o]     = s0;
                    ps[wn * 512 + b * 128 + o + 8] = s1;
                }
            }
        }
        __syncthreads();
        #pragma unroll
        for (int r = 0; r < 2; r++) {
            int idx = r * THREADS + tid;        // 0..511
            int b = idx >> 7, row = idx & 127;
            out[(size_t)(bbase + b) * 192 + 64 + row] = ps[idx] + ps[512 + idx];
        }
    }
}

// ---------------- launch ----------------
extern "C" void kernel_launch(void* const* d_in, const int* in_sizes, int n_in,
                              void* d_out, int out_size) {
    const float* xg = (const float*)d_in[0];   // (2048,32,64)
    const float* W0 = (const float*)d_in[1];   // (128,1024)
    const float* b0 = (const float*)d_in[2];   // (128)
    const float* W1 = (const float*)d_in[3];   // (128,2048)
    const float* b1 = (const float*)d_in[4];   // (128)
    float* out = (float*)d_out;                // (2048,192)

    prep_kernel<<<1536, 256>>>(W0, W1);

    cudaFuncSetAttribute((const void*)cin_mma_kernel,
                         cudaFuncAttributeMaxDynamicSharedMemorySize, SMEM_TOTAL);
    cin_mma_kernel<<<2048 / NB, THREADS, SMEM_TOTAL>>>(xg, b0, b1, out);
}

// round 6
// speedup vs baseline: 1.3656x; 1.3656x over previous
#include <cuda_runtime.h>
#include <cuda_bf16.h>
#include <cstdint>

// ---------------- configuration ----------------
#define NB      4            // batches per CTA
#define THREADS 256
#define HPAD    65           // h row pitch (floats)
#define NT0     16           // layer-0 K tiles (K=1024, 64 k per tile)
#define NT_ALL  48           // + 32 layer-1 tiles (K=2048)
#define NITER   192          // NT_ALL * NB
#define WPITCH  144          // W/z row pitch in bytes (72 bf16)
#define WPLANE  18432        // 128 rows * 144B  (one bf16 plane of a W tile)
#define WTILE   36864        // hi+lo planes
#define ZPLANE  9216         // 64 rows * 144B
#define ZTILE   18432        // hi+lo planes

// dynamic smem byte offsets
#define OFF_X   0            // 4 * 8192   x fp32 [32][64] per batch
#define OFF_H   32768        // 4 * 16640  h fp32 [64][HPAD] per batch
#define OFF_W   99328        // 2 * WTILE
#define OFF_Z   173056       // 2 * ZTILE   (epilogue partial sums overlay here)
#define SMEM_TOTAL 209920

// pre-split W: 48 tiles, each [hi plane 128x144B][lo plane 128x144B]
__device__ __align__(16) unsigned char g_Wpre[48 * WTILE];

// ---------------- helpers ----------------
static __device__ __forceinline__ uint32_t smem_u32(const void* p) {
    return (uint32_t)__cvta_generic_to_shared(p);
}
static __device__ __forceinline__ void cpa16(uint32_t dst, const void* src) {
    asm volatile("cp.async.cg.shared.global [%0], [%1], 16;" :: "r"(dst), "l"(src));
}
static __device__ __forceinline__ void cp_commit() { asm volatile("cp.async.commit_group;"); }
template <int N>
static __device__ __forceinline__ void cp_wait() { asm volatile("cp.async.wait_group %0;" :: "n"(N)); }

static __device__ __forceinline__ void sts128(uint32_t a, uint32_t r0, uint32_t r1, uint32_t r2, uint32_t r3) {
    asm volatile("st.shared.v4.b32 [%0], {%1, %2, %3, %4};" :: "r"(a), "r"(r0), "r"(r1), "r"(r2), "r"(r3));
}
// 4x m8n8 b16 matrices; volatile => ordered w.r.t. barriers & sts (both volatile)
static __device__ __forceinline__ void ldmx4(uint32_t* r, uint32_t a) {
    asm volatile("ldmatrix.sync.aligned.m8n8.x4.shared.b16 {%0,%1,%2,%3}, [%4];"
        : "=r"(r[0]), "=r"(r[1]), "=r"(r[2]), "=r"(r[3]) : "r"(a));
}
// m16n8k16 row.col bf16 -> f32, D += A*B (register-pure; NON-volatile so the
// scheduler can interleave z-build FMA/CVT work under MMA issue)
static __device__ __forceinline__ void mma16816(float* c, const uint32_t* a, const uint32_t* b) {
    asm("mma.sync.aligned.m16n8k16.row.col.f32.bf16.bf16.f32 "
        "{%0,%1,%2,%3}, {%4,%5,%6,%7}, {%8,%9}, {%0,%1,%2,%3};"
        : "+f"(c[0]), "+f"(c[1]), "+f"(c[2]), "+f"(c[3])
        : "r"(a[0]), "r"(a[1]), "r"(a[2]), "r"(a[3]), "r"(b[0]), "r"(b[1]));
}

// ---------------- prep: split W into bf16 hi/lo, padded-pitch tiles ----------------
__global__ void prep_kernel(const float* __restrict__ W0, const float* __restrict__ W1) {
    int idx = blockIdx.x * 256 + threadIdx.x;      // 0..393215
    float w; int o, k; size_t base;
    if (idx < 131072) { o = idx >> 10; k = idx & 1023; w = W0[idx]; base = (size_t)(k >> 6) * WTILE; }
    else { int j = idx - 131072; o = j >> 11; k = j & 2047; w = W1[j]; base = 16 * WTILE + (size_t)(k >> 6) * WTILE; }
    __nv_bfloat16 hi = __float2bfloat16(w);
    __nv_bfloat16 lo = __float2bfloat16(w - __bfloat162float(hi));
    int c = k & 63;
    size_t off = base + (size_t)o * WPITCH + (size_t)c * 2;
    *(__nv_bfloat16*)(g_Wpre + off)          = hi;
    *(__nv_bfloat16*)(g_Wpre + off + WPLANE) = lo;
}

// ---------------- main kernel ----------------
__global__ __launch_bounds__(THREADS, 1)
void cin_mma_kernel(const float* __restrict__ xg,
                    const float* __restrict__ b0g,
                    const float* __restrict__ b1g,
                    float* __restrict__ out)
{
    extern __shared__ __align__(256) unsigned char smem[];
    const uint32_t sb = smem_u32(smem);
    const int tid  = threadIdx.x;
    const int wid  = tid >> 5;
    const int lane = tid & 31;
    const int lr   = lane >> 2;     // fragment row within 8
    const int lc   = lane & 3;      // fragment col group

    const int wo = wid >> 1;        // warp o-tile (0..3) -> o base wo*32
    const int wn = wid & 1;         // warp n-tile (0..1) -> d base wn*32

    // ldmatrix per-lane address offsets
    const uint32_t aOff = (uint32_t)((lane & 15) * WPITCH + ((lane & 16) ? 16 : 0));
    const uint32_t bOff = (uint32_t)(((lane & 7) + ((lane & 16) >> 1)) * WPITCH + ((lane & 8) << 1));

    float* xs = (float*)(smem + OFF_X);
    float* hs = (float*)(smem + OFF_H);

    const int bbase = blockIdx.x * NB;

    // initial loads: x (32KB) + W tile 0, one cp.async group
    {
        const char* src = (const char*)(xg + (size_t)bbase * 2048);
        #pragma unroll
        for (int r = 0; r < 8; r++)
            cpa16(sb + OFF_X + (uint32_t)(r * THREADS + tid) * 16, src + (size_t)(r * THREADS + tid) * 16);
        #pragma unroll
        for (int r = 0; r < 9; r++) {
            int idx = r * THREADS + tid;
            if (idx < WTILE / 16)
                cpa16(sb + OFF_W + (uint32_t)idx * 16, g_Wpre + (size_t)idx * 16);
        }
        cp_commit();
    }

    // z producer mapping
    const int d  = tid & 63;
    const int kq = tid >> 6;        // 0..3 -> 16-k strip
    const int kb = kq * 16;
    const int m0 = (kq & 1) * 16;

    // build z tile for flat iter j into buffer (j&1). Never touches acc.
    auto build_z = [&](int j) {
        int gg = j >> 2, bz = j & 3;
        int gl = (gg < NT0) ? gg : gg - NT0;
        int hid = gl * 2 + (kq >> 1);
        const uint32_t zb = sb + OFF_Z + (uint32_t)(j & 1) * ZTILE;
        const float* xb = xs + (size_t)bz * 2048;
        const float* hrow = (gg < NT0) ? (xb + hid * 64)
                                       : (hs + (size_t)bz * (64 * HPAD) + hid * HPAD);
        const float xh = hrow[d];
        uint32_t hi[8], lo[8];
        #pragma unroll
        for (int i = 0; i < 8; i++) {
            float z0 = xh * xb[(m0 + 2 * i) * 64 + d];
            float z1 = xh * xb[(m0 + 2 * i + 1) * 64 + d];
            uint32_t p0; asm("cvt.rn.bf16x2.f32 %0, %1, %2;" : "=r"(p0) : "f"(z1), "f"(z0));
            float r0 = z0 - __uint_as_float(p0 << 16);
            float r1 = z1 - __uint_as_float(p0 & 0xFFFF0000u);
            uint32_t p1; asm("cvt.rn.bf16x2.f32 %0, %1, %2;" : "=r"(p1) : "f"(r1), "f"(r0));
            hi[i] = p0; lo[i] = p1;
        }
        uint32_t a0 = zb + (uint32_t)(d * WPITCH + kb * 2);
        sts128(a0,               hi[0], hi[1], hi[2], hi[3]);
        sts128(a0 + 16,          hi[4], hi[5], hi[6], hi[7]);
        sts128(a0 + ZPLANE,      lo[0], lo[1], lo[2], lo[3]);
        sts128(a0 + ZPLANE + 16, lo[4], lo[5], lo[6], lo[7]);
    };

    float acc[NB][2][4][4];      // statically indexed ONLY (b from unrolled loop)
    #pragma unroll
    for (int b = 0; b < NB; b++)
        #pragma unroll
        for (int mi = 0; mi < 2; mi++)
            #pragma unroll
            for (int nj = 0; nj < 4; nj++)
                #pragma unroll
                for (int q = 0; q < 4; q++) acc[b][mi][nj][q] = 0.0f;

    cp_wait<0>();          // x + W tile 0 resident
    __syncthreads();
    build_z(0);

    for (int g = 0; g < NT_ALL; g++) {
        if (g > 0) cp_wait<0>();          // W(g) resident (prefetched during g-1)
        const uint32_t wtile = sb + OFF_W + (uint32_t)(g & 1) * WTILE;
        const uint32_t aBase = wtile + (uint32_t)(wo * 32 * WPITCH) + aOff;

        #pragma unroll
        for (int b = 0; b < NB; b++) {     // b is COMPILE-TIME -> acc[b] stays in regs
            const int i = g * 4 + b;
            __syncthreads();               // z(i) visible; z(i-1) readers done

            // pipeline: build z(i+1) (FMA/CVT overlaps MMA issue below)
            if (i + 1 < NITER && i != 63) build_z(i + 1);

            if (b == 0 && g + 1 < NT_ALL) {    // prefetch next W tile
                const unsigned char* src = g_Wpre + (size_t)(g + 1) * WTILE;
                uint32_t dst = sb + OFF_W + (uint32_t)((g + 1) & 1) * WTILE;
                #pragma unroll
                for (int r = 0; r < 9; r++) {
                    int idx = r * THREADS + tid;
                    if (idx < WTILE / 16)
                        cpa16(dst + (uint32_t)idx * 16, src + (size_t)idx * 16);
                }
                cp_commit();
            }

            // ---- MMA block for iter i (reads z buffer i&1 = b&1)
            {
                const uint32_t zbuf  = sb + OFF_Z + (uint32_t)(b & 1) * ZTILE;
                const uint32_t bBase = zbuf + (uint32_t)(wn * 32 * WPITCH) + bOff;
                #pragma unroll
                for (int ks = 0; ks < 4; ks++) {
                    uint32_t Ah0[4], Ah1[4], Al0[4], Al1[4];
                    uint32_t Bh01[4], Bh23[4], Bl01[4], Bl23[4];
                    const uint32_t ab = aBase + (uint32_t)(ks * 32);
                    const uint32_t bbs = bBase + (uint32_t)(ks * 32);
                    ldmx4(Ah0, ab);
                    ldmx4(Ah1, ab + 16 * WPITCH);
                    ldmx4(Al0, ab + WPLANE);
                    ldmx4(Al1, ab + WPLANE + 16 * WPITCH);
                    ldmx4(Bh01, bbs);
                    ldmx4(Bh23, bbs + 16 * WPITCH);
                    ldmx4(Bl01, bbs + ZPLANE);
                    ldmx4(Bl23, bbs + ZPLANE + 16 * WPITCH);
                    // pass 1: Ahi * Bhi
                    mma16816(acc[b][0][0], Ah0, Bh01);     mma16816(acc[b][0][1], Ah0, Bh01 + 2);
                    mma16816(acc[b][0][2], Ah0, Bh23);     mma16816(acc[b][0][3], Ah0, Bh23 + 2);
                    mma16816(acc[b][1][0], Ah1, Bh01);     mma16816(acc[b][1][1], Ah1, Bh01 + 2);
                    mma16816(acc[b][1][2], Ah1, Bh23);     mma16816(acc[b][1][3], Ah1, Bh23 + 2);
                    // pass 2: Ahi * Blo
                    mma16816(acc[b][0][0], Ah0, Bl01);     mma16816(acc[b][0][1], Ah0, Bl01 + 2);
                    mma16816(acc[b][0][2], Ah0, Bl23);     mma16816(acc[b][0][3], Ah0, Bl23 + 2);
                    mma16816(acc[b][1][0], Ah1, Bl01);     mma16816(acc[b][1][1], Ah1, Bl01 + 2);
                    mma16816(acc[b][1][2], Ah1, Bl23);     mma16816(acc[b][1][3], Ah1, Bl23 + 2);
                    // pass 3: Alo * Bhi
                    mma16816(acc[b][0][0], Al0, Bh01);     mma16816(acc[b][0][1], Al0, Bh01 + 2);
                    mma16816(acc[b][0][2], Al0, Bh23);     mma16816(acc[b][0][3], Al0, Bh23 + 2);
                    mma16816(acc[b][1][0], Al1, Bh01);     mma16816(acc[b][1][1], Al1, Bh01 + 2);
                    mma16816(acc[b][1][2], Al1, Bh23);     mma16816(acc[b][1][3], Al1, Bh23 + 2);
                }
            }

            if (g == NT0 - 1 && b == 3) {
                // ======== layer-0 epilogue (i == 63) ========
                __syncthreads();                        // all iter-63 smem reads done
                float* ps = (float*)(smem + OFF_Z);     // partial sums overlay (buf0)
                #pragma unroll
                for (int bb = 0; bb < NB; bb++) {
                    #pragma unroll
                    for (int mi = 0; mi < 2; mi++) {
                        int o  = wo * 32 + mi * 16 + lr;
                        float bias0 = b0g[o], bias1 = b0g[o + 8];
                        if (wo < 2) {
                            float* h0 = hs + (size_t)bb * (64 * HPAD) + o * HPAD;
                            float* h1 = h0 + 8 * HPAD;
                            #pragma unroll
                            for (int nj = 0; nj < 4; nj++) {
                                int dd = wn * 32 + nj * 8 + 2 * lc;
                                h0[dd]     = fmaxf(acc[bb][mi][nj][0] + bias0, 0.0f);
                                h0[dd + 1] = fmaxf(acc[bb][mi][nj][1] + bias0, 0.0f);
                                h1[dd]     = fmaxf(acc[bb][mi][nj][2] + bias1, 0.0f);
                                h1[dd + 1] = fmaxf(acc[bb][mi][nj][3] + bias1, 0.0f);
                            }
                        } else {
                            float s0 = 0.0f, s1 = 0.0f;
                            #pragma unroll
                            for (int nj = 0; nj < 4; nj++) {
                                s0 += fmaxf(acc[bb][mi][nj][0] + bias0, 0.0f)
                                    + fmaxf(acc[bb][mi][nj][1] + bias0, 0.0f);
                                s1 += fmaxf(acc[bb][mi][nj][2] + bias1, 0.0f)
                                    + fmaxf(acc[bb][mi][nj][3] + bias1, 0.0f);
                            }
                            s0 += __shfl_xor_sync(0xffffffffu, s0, 1);
                            s0 += __shfl_xor_sync(0xffffffffu, s0, 2);
                            s1 += __shfl_xor_sync(0xffffffffu, s1, 1);
                            s1 += __shfl_xor_sync(0xffffffffu, s1, 2);
                            if (lc == 0) {
                                int row = (wo - 2) * 32 + mi * 16 + lr;
                                ps[wn * 256 + bb * 64 + row]     = s0;
                                ps[wn * 256 + bb * 64 + row + 8] = s1;
                            }
                        }
                    }
                }
                __syncthreads();
                {
                    int bb = tid >> 6, row = tid & 63;
                    out[(size_t)(bbase + bb) * 192 + row] = ps[bb * 64 + row] + ps[256 + bb * 64 + row];
                }
                // reset accumulators for layer 1
                #pragma unroll
                for (int bb = 0; bb < NB; bb++)
                    #pragma unroll
                    for (int mi = 0; mi < 2; mi++)
                        #pragma unroll
                        for (int nj = 0; nj < 4; nj++)
                            #pragma unroll
                            for (int q = 0; q < 4; q++) acc[bb][mi][nj][q] = 0.0f;
                __syncthreads();      // ps reads done before z(64) overwrites buf0
                build_z(64);          // uses hs written above
            }
        }
    }

    // ======== layer-1 epilogue: out rows 64..191 ========
    __syncthreads();
    {
        float* ps = (float*)(smem + OFF_Z);   // [wn][b][row<128]
        #pragma unroll
        for (int b = 0; b < NB; b++) {
            #pragma unroll
            for (int mi = 0; mi < 2; mi++) {
                int o = wo * 32 + mi * 16 + lr;
                float bias0 = b1g[o], bias1 = b1g[o + 8];
                float s0 = 0.0f, s1 = 0.0f;
                #pragma unroll
                for (int nj = 0; nj < 4; nj++) {
                    s0 += fmaxf(acc[b][mi][nj][0] + bias0, 0.0f)
                        + fmaxf(acc[b][mi][nj][1] + bias0, 0.0f);
                    s1 += fmaxf(acc[b][mi][nj][2] + bias1, 0.0f)
                        + fmaxf(acc[b][mi][nj][3] + bias1, 0.0f);
                }
                s0 += __shfl_xor_sync(0xffffffffu, s0, 1);
                s0 += __shfl_xor_sync(0xffffffffu, s0, 2);
                s1 += __shfl_xor_sync(0xffffffffu, s1, 1);
                s1 += __shfl_xor_sync(0xffffffffu, s1, 2);
                if (lc == 0) {
                    ps[wn * 512 + b * 128 + o]     = s0;
                    ps[wn * 512 + b * 128 + o + 8] = s1;
                }
            }
        }
        __syncthreads();
        #pragma unroll
        for (int r = 0; r < 2; r++) {
            int idx = r * THREADS + tid;        // 0..511
            int b = idx >> 7, row = idx & 127;
            out[(size_t)(bbase + b) * 192 + 64 + row] = ps[idx] + ps[512 + idx];
        }
    }
}

// ---------------- launch ----------------
extern "C" void kernel_launch(void* const* d_in, const int* in_sizes, int n_in,
                              void* d_out, int out_size) {
    const float* xg = (const float*)d_in[0];   // (2048,32,64)
    const float* W0 = (const float*)d_in[1];   // (128,1024)
    const float* b0 = (const float*)d_in[2];   // (128)
    const float* W1 = (const float*)d_in[3];   // (128,2048)
    const float* b1 = (const float*)d_in[4];   // (128)
    float* out = (float*)d_out;                // (2048,192)

    prep_kernel<<<1536, 256>>>(W0, W1);

    cudaFuncSetAttribute((const void*)cin_mma_kernel,
                         cudaFuncAttributeMaxDynamicSharedMemorySize, SMEM_TOTAL);
    cin_mma_kernel<<<2048 / NB, THREADS, SMEM_TOTAL>>>(xg, b0, b1, out);
}

// round 7
// speedup vs baseline: 1.7300x; 1.2669x over previous
#include <cuda_runtime.h>
#include <cuda_bf16.h>
#include <cstdint>

// ---------------- configuration ----------------
#define NB      2            // batches per CTA
#define THREADS 256
#define HPAD    65           // h row pitch (floats)
#define NT0     32           // layer-0 K tiles (K=1024, 32 k per tile = one h row)
#define NT_ALL  96           // + 64 layer-1 tiles (K=2048)
#define NITER   192          // NT_ALL * NB
#define WPITCH  80           // W/z row pitch in bytes (64B data + 16B pad; conflict-free)
#define WPLANE  10240        // 128 rows * 80B (one bf16 plane of a W tile)
#define WTILE   20480        // hi+lo planes
#define ZPLANE  5120         // 64 rows * 80B
#define ZTILE   10240        // hi+lo planes

// dynamic smem byte offsets (2 CTAs/SM: total 111104B = 108.5KB)
#define OFF_X   0            // 2 * 8192   x fp32 [32][64] per batch
#define OFF_H   16384        // 2 * 16640  h fp32 [64][HPAD] per batch
#define OFF_W   49664        // 2 * WTILE
#define OFF_Z   90624        // 2 * ZTILE  (epilogue partial sums overlay here)
#define SMEM_TOTAL 111104

// pre-split W: 96 tiles, each [hi plane 128x80B][lo plane 128x80B]
__device__ __align__(16) unsigned char g_Wpre[96 * WTILE];

// ---------------- helpers ----------------
static __device__ __forceinline__ uint32_t smem_u32(const void* p) {
    return (uint32_t)__cvta_generic_to_shared(p);
}
static __device__ __forceinline__ void cpa16(uint32_t dst, const void* src) {
    asm volatile("cp.async.cg.shared.global [%0], [%1], 16;" :: "r"(dst), "l"(src));
}
static __device__ __forceinline__ void cp_commit() { asm volatile("cp.async.commit_group;"); }
template <int N>
static __device__ __forceinline__ void cp_wait() { asm volatile("cp.async.wait_group %0;" :: "n"(N)); }

static __device__ __forceinline__ void sts128(uint32_t a, uint32_t r0, uint32_t r1, uint32_t r2, uint32_t r3) {
    asm volatile("st.shared.v4.b32 [%0], {%1, %2, %3, %4};" :: "r"(a), "r"(r0), "r"(r1), "r"(r2), "r"(r3));
}
static __device__ __forceinline__ void ldmx4(uint32_t* r, uint32_t a) {
    asm volatile("ldmatrix.sync.aligned.m8n8.x4.shared.b16 {%0,%1,%2,%3}, [%4];"
        : "=r"(r[0]), "=r"(r[1]), "=r"(r[2]), "=r"(r[3]) : "r"(a));
}
// m16n8k16 row.col bf16 -> f32, D += A*B (register-pure)
static __device__ __forceinline__ void mma16816(float* c, const uint32_t* a, const uint32_t* b) {
    asm("mma.sync.aligned.m16n8k16.row.col.f32.bf16.bf16.f32 "
        "{%0,%1,%2,%3}, {%4,%5,%6,%7}, {%8,%9}, {%0,%1,%2,%3};"
        : "+f"(c[0]), "+f"(c[1]), "+f"(c[2]), "+f"(c[3])
        : "r"(a[0]), "r"(a[1]), "r"(a[2]), "r"(a[3]), "r"(b[0]), "r"(b[1]));
}

// ---------------- prep: split W into bf16 hi/lo, 32-k pitch-80 tiles ----------------
__global__ void prep_kernel(const float* __restrict__ W0, const float* __restrict__ W1) {
    int idx = blockIdx.x * 256 + threadIdx.x;      // 0..393215
    float w; int o, k; size_t base;
    if (idx < 131072) { o = idx >> 10; k = idx & 1023; w = W0[idx]; base = (size_t)(k >> 5) * WTILE; }
    else { int j = idx - 131072; o = j >> 11; k = j & 2047; w = W1[j]; base = (size_t)(32 + (k >> 5)) * WTILE; }
    __nv_bfloat16 hi = __float2bfloat16(w);
    __nv_bfloat16 lo = __float2bfloat16(w - __bfloat162float(hi));
    int c = k & 31;
    size_t off = base + (size_t)o * WPITCH + (size_t)c * 2;
    *(__nv_bfloat16*)(g_Wpre + off)          = hi;
    *(__nv_bfloat16*)(g_Wpre + off + WPLANE) = lo;
}

// ---------------- main kernel ----------------
__global__ __launch_bounds__(THREADS, 2)
void cin_mma_kernel(const float* __restrict__ xg,
                    const float* __restrict__ b0g,
                    const float* __restrict__ b1g,
                    float* __restrict__ out)
{
    extern __shared__ __align__(256) unsigned char smem[];
    const uint32_t sb = smem_u32(smem);
    const int tid  = threadIdx.x;
    const int wid  = tid >> 5;
    const int lane = tid & 31;
    const int lr   = lane >> 2;
    const int lc   = lane & 3;

    const int wo = wid >> 1;        // warp o-tile (0..3) -> o base wo*32
    const int wn = wid & 1;         // warp n-tile (0..1) -> d base wn*32

    // ldmatrix per-lane address offsets (pitch 80)
    const uint32_t aOff = (uint32_t)((lane & 15) * WPITCH + ((lane & 16) ? 16 : 0));
    const uint32_t bOff = (uint32_t)(((lane & 7) + ((lane & 16) >> 1)) * WPITCH + ((lane & 8) << 1));

    float* xs = (float*)(smem + OFF_X);
    float* hs = (float*)(smem + OFF_H);

    const int bbase = blockIdx.x * NB;

    // initial loads: x (16KB, 4/thread) + W tile 0 (20KB, 5/thread), one group
    {
        const char* src = (const char*)(xg + (size_t)bbase * 2048);
        #pragma unroll
        for (int r = 0; r < 4; r++)
            cpa16(sb + OFF_X + (uint32_t)(r * THREADS + tid) * 16, src + (size_t)(r * THREADS + tid) * 16);
        #pragma unroll
        for (int r = 0; r < 5; r++)
            cpa16(sb + OFF_W + (uint32_t)(r * THREADS + tid) * 16, g_Wpre + (size_t)(r * THREADS + tid) * 16);
        cp_commit();
    }

    // z producer mapping: thread covers 8 consecutive m within tile's h-row
    const int d  = tid & 63;
    const int m0 = (tid >> 6) * 8;

    // build z tile for flat iter j into buffer (j&1). Never touches acc.
    auto build_z = [&](int j) {
        int gg = j >> 1, bz = j & 1;
        int gl = (gg < NT0) ? gg : gg - NT0;
        const uint32_t zb = sb + OFF_Z + (uint32_t)(j & 1) * ZTILE;
        const float* xb = xs + (size_t)bz * 2048;
        const float xh = (gg < NT0) ? xb[gl * 64 + d]
                                    : hs[(size_t)bz * (64 * HPAD) + gl * HPAD + d];
        uint32_t hi[4], lo[4];
        #pragma unroll
        for (int i = 0; i < 4; i++) {
            float z0 = xh * xb[(m0 + 2 * i) * 64 + d];
            float z1 = xh * xb[(m0 + 2 * i + 1) * 64 + d];
            uint32_t p0; asm("cvt.rn.bf16x2.f32 %0, %1, %2;" : "=r"(p0) : "f"(z1), "f"(z0));
            float r0 = z0 - __uint_as_float(p0 << 16);
            float r1 = z1 - __uint_as_float(p0 & 0xFFFF0000u);
            uint32_t p1; asm("cvt.rn.bf16x2.f32 %0, %1, %2;" : "=r"(p1) : "f"(r1), "f"(r0));
            hi[i] = p0; lo[i] = p1;
        }
        uint32_t a0 = zb + (uint32_t)(d * WPITCH + m0 * 2);
        sts128(a0,          hi[0], hi[1], hi[2], hi[3]);
        sts128(a0 + ZPLANE, lo[0], lo[1], lo[2], lo[3]);
    };

    float acc[NB][2][4][4];      // statically indexed ONLY
    #pragma unroll
    for (int b = 0; b < NB; b++)
        #pragma unroll
        for (int mi = 0; mi < 2; mi++)
            #pragma unroll
            for (int nj = 0; nj < 4; nj++)
                #pragma unroll
                for (int q = 0; q < 4; q++) acc[b][mi][nj][q] = 0.0f;

    cp_wait<0>();
    __syncthreads();
    build_z(0);

    for (int g = 0; g < NT_ALL; g++) {
        if (g > 0) cp_wait<0>();          // W(g) resident (prefetched during g-1)
        const uint32_t wtile = sb + OFF_W + (uint32_t)(g & 1) * WTILE;
        const uint32_t aBase = wtile + (uint32_t)(wo * 32 * WPITCH) + aOff;

        #pragma unroll
        for (int b = 0; b < NB; b++) {    // compile-time b -> acc in regs
            const int i = g * 2 + b;
            __syncthreads();              // z(i) visible; z(i-1) readers done

            if (i + 1 < NITER && i != 63) build_z(i + 1);

            if (b == 0 && g + 1 < NT_ALL) {    // prefetch next W tile (5/thread)
                const unsigned char* src = g_Wpre + (size_t)(g + 1) * WTILE;
                uint32_t dst = sb + OFF_W + (uint32_t)((g + 1) & 1) * WTILE;
                #pragma unroll
                for (int r = 0; r < 5; r++)
                    cpa16(dst + (uint32_t)(r * THREADS + tid) * 16, src + (size_t)(r * THREADS + tid) * 16);
                cp_commit();
            }

            // ---- MMA block for iter i (z buffer b)
            {
                const uint32_t zbuf  = sb + OFF_Z + (uint32_t)b * ZTILE;
                const uint32_t bBase = zbuf + (uint32_t)(wn * 32 * WPITCH) + bOff;
                #pragma unroll
                for (int ks = 0; ks < 2; ks++) {
                    uint32_t Ah0[4], Ah1[4], Al0[4], Al1[4];
                    uint32_t Bh01[4], Bh23[4], Bl01[4], Bl23[4];
                    const uint32_t ab  = aBase + (uint32_t)(ks * 32);
                    const uint32_t bbs = bBase + (uint32_t)(ks * 32);
                    ldmx4(Ah0, ab);
                    ldmx4(Ah1, ab + 16 * WPITCH);
                    ldmx4(Al0, ab + WPLANE);
                    ldmx4(Al1, ab + WPLANE + 16 * WPITCH);
                    ldmx4(Bh01, bbs);
                    ldmx4(Bh23, bbs + 16 * WPITCH);
                    ldmx4(Bl01, bbs + ZPLANE);
                    ldmx4(Bl23, bbs + ZPLANE + 16 * WPITCH);
                    // pass 1: Ahi * Bhi
                    mma16816(acc[b][0][0], Ah0, Bh01);     mma16816(acc[b][0][1], Ah0, Bh01 + 2);
                    mma16816(acc[b][0][2], Ah0, Bh23);     mma16816(acc[b][0][3], Ah0, Bh23 + 2);
                    mma16816(acc[b][1][0], Ah1, Bh01);     mma16816(acc[b][1][1], Ah1, Bh01 + 2);
                    mma16816(acc[b][1][2], Ah1, Bh23);     mma16816(acc[b][1][3], Ah1, Bh23 + 2);
                    // pass 2: Ahi * Blo
                    mma16816(acc[b][0][0], Ah0, Bl01);     mma16816(acc[b][0][1], Ah0, Bl01 + 2);
                    mma16816(acc[b][0][2], Ah0, Bl23);     mma16816(acc[b][0][3], Ah0, Bl23 + 2);
                    mma16816(acc[b][1][0], Ah1, Bl01);     mma16816(acc[b][1][1], Ah1, Bl01 + 2);
                    mma16816(acc[b][1][2], Ah1, Bl23);     mma16816(acc[b][1][3], Ah1, Bl23 + 2);
                    // pass 3: Alo * Bhi
                    mma16816(acc[b][0][0], Al0, Bh01);     mma16816(acc[b][0][1], Al0, Bh01 + 2);
                    mma16816(acc[b][0][2], Al0, Bh23);     mma16816(acc[b][0][3], Al0, Bh23 + 2);
                    mma16816(acc[b][1][0], Al1, Bh01);     mma16816(acc[b][1][1], Al1, Bh01 + 2);
                    mma16816(acc[b][1][2], Al1, Bh23);     mma16816(acc[b][1][3], Al1, Bh23 + 2);
                }
            }

            if (g == NT0 - 1 && b == 1) {
                // ======== layer-0 epilogue (i == 63) ========
                __syncthreads();                        // all iter-63 smem reads done
                float* ps = (float*)(smem + OFF_Z);     // overlay: 2*2*64 floats
                #pragma unroll
                for (int bb = 0; bb < NB; bb++) {
                    #pragma unroll
                    for (int mi = 0; mi < 2; mi++) {
                        int o  = wo * 32 + mi * 16 + lr;
                        float bias0 = b0g[o], bias1 = b0g[o + 8];
                        if (wo < 2) {
                            float* h0 = hs + (size_t)bb * (64 * HPAD) + o * HPAD;
                            float* h1 = h0 + 8 * HPAD;
                            #pragma unroll
                            for (int nj = 0; nj < 4; nj++) {
                                int dd = wn * 32 + nj * 8 + 2 * lc;
                                h0[dd]     = fmaxf(acc[bb][mi][nj][0] + bias0, 0.0f);
                                h0[dd + 1] = fmaxf(acc[bb][mi][nj][1] + bias0, 0.0f);
                                h1[dd]     = fmaxf(acc[bb][mi][nj][2] + bias1, 0.0f);
                                h1[dd + 1] = fmaxf(acc[bb][mi][nj][3] + bias1, 0.0f);
                            }
                        } else {
                            float s0 = 0.0f, s1 = 0.0f;
                            #pragma unroll
                            for (int nj = 0; nj < 4; nj++) {
                                s0 += fmaxf(acc[bb][mi][nj][0] + bias0, 0.0f)
                                    + fmaxf(acc[bb][mi][nj][1] + bias0, 0.0f);
                                s1 += fmaxf(acc[bb][mi][nj][2] + bias1, 0.0f)
                                    + fmaxf(acc[bb][mi][nj][3] + bias1, 0.0f);
                            }
                            s0 += __shfl_xor_sync(0xffffffffu, s0, 1);
                            s0 += __shfl_xor_sync(0xffffffffu, s0, 2);
                            s1 += __shfl_xor_sync(0xffffffffu, s1, 1);
                            s1 += __shfl_xor_sync(0xffffffffu, s1, 2);
                            if (lc == 0) {
                                int row = (wo - 2) * 32 + mi * 16 + lr;
                                ps[wn * 128 + bb * 64 + row]     = s0;
                                ps[wn * 128 + bb * 64 + row + 8] = s1;
                            }
                        }
                    }
                }
                __syncthreads();
                if (tid < 128) {
                    int bb = tid >> 6, row = tid & 63;
                    out[(size_t)(bbase + bb) * 192 + row] = ps[bb * 64 + row] + ps[128 + bb * 64 + row];
                }
                // reset accumulators for layer 1
                #pragma unroll
                for (int bb = 0; bb < NB; bb++)
                    #pragma unroll
                    for (int mi = 0; mi < 2; mi++)
                        #pragma unroll
                        for (int nj = 0; nj < 4; nj++)
                            #pragma unroll
                            for (int q = 0; q < 4; q++) acc[bb][mi][nj][q] = 0.0f;
                __syncthreads();      // ps reads done before z(64) overwrites buf0
                build_z(64);          // uses hs written above
            }
        }
    }

    // ======== layer-1 epilogue: out rows 64..191 ========
    __syncthreads();
    {
        float* ps = (float*)(smem + OFF_Z);   // 2*2*128 floats
        #pragma unroll
        for (int b = 0; b < NB; b++) {
            #pragma unroll
            for (int mi = 0; mi < 2; mi++) {
                int o = wo * 32 + mi * 16 + lr;
                float bias0 = b1g[o], bias1 = b1g[o + 8];
                float s0 = 0.0f, s1 = 0.0f;
                #pragma unroll
                for (int nj = 0; nj < 4; nj++) {
                    s0 += fmaxf(acc[b][mi][nj][0] + bias0, 0.0f)
                        + fmaxf(acc[b][mi][nj][1] + bias0, 0.0f);
                    s1 += fmaxf(acc[b][mi][nj][2] + bias1, 0.0f)
                        + fmaxf(acc[b][mi][nj][3] + bias1, 0.0f);
                }
                s0 += __shfl_xor_sync(0xffffffffu, s0, 1);
                s0 += __shfl_xor_sync(0xffffffffu, s0, 2);
                s1 += __shfl_xor_sync(0xffffffffu, s1, 1);
                s1 += __shfl_xor_sync(0xffffffffu, s1, 2);
                if (lc == 0) {
                    ps[wn * 256 + b * 128 + o]     = s0;
                    ps[wn * 256 + b * 128 + o + 8] = s1;
                }
            }
        }
        __syncthreads();
        {
            int b = tid >> 7, row = tid & 127;
            out[(size_t)(bbase + b) * 192 + 64 + row] = ps[tid] + ps[256 + tid];
        }
    }
}

// ---------------- launch ----------------
extern "C" void kernel_launch(void* const* d_in, const int* in_sizes, int n_in,
                              void* d_out, int out_size) {
    const float* xg = (const float*)d_in[0];   // (2048,32,64)
    const float* W0 = (const float*)d_in[1];   // (128,1024)
    const float* b0 = (const float*)d_in[2];   // (128)
    const float* W1 = (const float*)d_in[3];   // (128,2048)
    const float* b1 = (const float*)d_in[4];   // (128)
    float* out = (float*)d_out;                // (2048,192)

    prep_kernel<<<1536, 256>>>(W0, W1);

    cudaFuncSetAttribute((const void*)cin_mma_kernel,
                         cudaFuncAttributeMaxDynamicSharedMemorySize, SMEM_TOTAL);
    cin_mma_kernel<<<2048 / NB, THREADS, SMEM_TOTAL>>>(xg, b0, b1, out);
}

// round 8
// speedup vs baseline: 2.1270x; 1.2295x over previous
#include <cuda_runtime.h>
#include <cuda_bf16.h>
#include <cstdint>

// ---------------- configuration ----------------
#define NB      2            // batches per CTA
#define THREADS 256
#define HPAD    65           // h row pitch (floats)
#define NT0     32           // layer-0 K tiles (K=1024, 32 k per tile = one h row)
#define NT_ALL  96           // + 64 layer-1 tiles (K=2048)
#define NITER   192          // NT_ALL * NB
#define WPITCH  144          // W/z row pitch in bytes (128B tf32 data + 16B pad)
#define WTILE   18432        // 128 rows * 144B (tf32 W tile, 32 k)
#define ZTILE   9216         // 64 rows * 144B  (tf32 z tile)

// dynamic smem byte offsets (2 CTAs/SM: 104960B = 102.5KB per CTA)
#define OFF_X   0            // 2 * 8192   x fp32 [32][64] per batch
#define OFF_H   16384        // 2 * 16640  h fp32 [64][HPAD] per batch
#define OFF_W   49664        // 2 * WTILE
#define OFF_Z   86528        // 2 * ZTILE  (epilogue partial sums overlay here)
#define SMEM_TOTAL 104960

// pre-converted W: 96 tf32 tiles (pitch 144)
__device__ __align__(16) unsigned char g_Wpre[96 * WTILE];

// ---------------- helpers ----------------
static __device__ __forceinline__ uint32_t smem_u32(const void* p) {
    return (uint32_t)__cvta_generic_to_shared(p);
}
static __device__ __forceinline__ void cpa16(uint32_t dst, const void* src) {
    asm volatile("cp.async.cg.shared.global [%0], [%1], 16;" :: "r"(dst), "l"(src));
}
static __device__ __forceinline__ void cp_commit() { asm volatile("cp.async.commit_group;"); }
template <int N>
static __device__ __forceinline__ void cp_wait() { asm volatile("cp.async.wait_group %0;" :: "n"(N)); }

static __device__ __forceinline__ void sts128(uint32_t a, uint32_t r0, uint32_t r1, uint32_t r2, uint32_t r3) {
    asm volatile("st.shared.v4.b32 [%0], {%1, %2, %3, %4};" :: "r"(a), "r"(r0), "r"(r1), "r"(r2), "r"(r3));
}
static __device__ __forceinline__ void ldmx4(uint32_t* r, uint32_t a) {
    asm volatile("ldmatrix.sync.aligned.m8n8.x4.shared.b16 {%0,%1,%2,%3}, [%4];"
        : "=r"(r[0]), "=r"(r[1]), "=r"(r[2]), "=r"(r[3]) : "r"(a));
}
static __device__ __forceinline__ uint32_t f2tf32(float f) {
    uint32_t r; asm("cvt.rna.tf32.f32 %0, %1;" : "=r"(r) : "f"(f)); return r;
}
// m16n8k8 row.col tf32 -> f32, D += A*B (register-pure)
static __device__ __forceinline__ void mma_tf32(float* c, const uint32_t* a, const uint32_t* b) {
    asm("mma.sync.aligned.m16n8k8.row.col.f32.tf32.tf32.f32 "
        "{%0,%1,%2,%3}, {%4,%5,%6,%7}, {%8,%9}, {%0,%1,%2,%3};"
        : "+f"(c[0]), "+f"(c[1]), "+f"(c[2]), "+f"(c[3])
        : "r"(a[0]), "r"(a[1]), "r"(a[2]), "r"(a[3]), "r"(b[0]), "r"(b[1]));
}

// ---------------- prep: round W to tf32, 32-k pitch-144 tiles ----------------
__global__ void prep_kernel(const float* __restrict__ W0, const float* __restrict__ W1) {
    int idx = blockIdx.x * 256 + threadIdx.x;      // 0..393215
    float w; int o, k; size_t base;
    if (idx < 131072) { o = idx >> 10; k = idx & 1023; w = W0[idx]; base = (size_t)(k >> 5) * WTILE; }
    else { int j = idx - 131072; o = j >> 11; k = j & 2047; w = W1[j]; base = (size_t)(32 + (k >> 5)) * WTILE; }
    *(uint32_t*)(g_Wpre + base + (size_t)o * WPITCH + (size_t)(k & 31) * 4) = f2tf32(w);
}

// ---------------- main kernel ----------------
__global__ __launch_bounds__(THREADS, 2)
void cin_mma_kernel(const float* __restrict__ xg,
                    const float* __restrict__ b0g,
                    const float* __restrict__ b1g,
                    float* __restrict__ out)
{
    extern __shared__ __align__(256) unsigned char smem[];
    const uint32_t sb = smem_u32(smem);
    const int tid  = threadIdx.x;
    const int wid  = tid >> 5;
    const int lane = tid & 31;
    const int lr   = lane >> 2;
    const int lc   = lane & 3;

    const int wo = wid >> 1;        // warp o-tile (0..3) -> o base wo*32
    const int wn = wid & 1;         // warp n-tile (0..1) -> d base wn*32

    // ldmatrix per-lane address offsets (tf32 slabs, pitch 144)
    const uint32_t aOff = (uint32_t)((lane & 15) * WPITCH + ((lane & 16) ? 16 : 0));
    const uint32_t bOff = (uint32_t)(((lane & 7) + ((lane & 16) >> 1)) * WPITCH + ((lane & 8) << 1));

    float* xs = (float*)(smem + OFF_X);
    float* hs = (float*)(smem + OFF_H);

    const int bbase = blockIdx.x * NB;

    // initial loads: x (16KB, 4/thread) + W tile 0 (18432B), one group
    {
        const char* src = (const char*)(xg + (size_t)bbase * 2048);
        #pragma unroll
        for (int r = 0; r < 4; r++)
            cpa16(sb + OFF_X + (uint32_t)(r * THREADS + tid) * 16, src + (size_t)(r * THREADS + tid) * 16);
        #pragma unroll
        for (int r = 0; r < 5; r++) {
            int idx = r * THREADS + tid;
            if (idx < WTILE / 16)
                cpa16(sb + OFF_W + (uint32_t)idx * 16, g_Wpre + (size_t)idx * 16);
        }
        cp_commit();
    }

    // z producer mapping: thread covers 8 consecutive m within tile's h-row
    const int d  = tid & 63;
    const int m0 = (tid >> 6) * 8;

    // build z tile for flat iter j into buffer (j&1). Never touches acc.
    auto build_z = [&](int j) {
        int gg = j >> 1, bz = j & 1;
        int gl = (gg < NT0) ? gg : gg - NT0;
        const uint32_t zb = sb + OFF_Z + (uint32_t)(j & 1) * ZTILE;
        const float* xb = xs + (size_t)bz * 2048;
        const float xh = (gg < NT0) ? xb[gl * 64 + d]
                                    : hs[(size_t)bz * (64 * HPAD) + gl * HPAD + d];
        uint32_t t[8];
        #pragma unroll
        for (int i = 0; i < 8; i++)
            t[i] = f2tf32(xh * xb[(m0 + i) * 64 + d]);
        uint32_t a0 = zb + (uint32_t)(d * WPITCH + m0 * 4);
        sts128(a0,      t[0], t[1], t[2], t[3]);
        sts128(a0 + 16, t[4], t[5], t[6], t[7]);
    };

    float acc[NB][2][4][4];      // statically indexed ONLY
    #pragma unroll
    for (int b = 0; b < NB; b++)
        #pragma unroll
        for (int mi = 0; mi < 2; mi++)
            #pragma unroll
            for (int nj = 0; nj < 4; nj++)
                #pragma unroll
                for (int q = 0; q < 4; q++) acc[b][mi][nj][q] = 0.0f;

    cp_wait<0>();
    __syncthreads();
    build_z(0);

    for (int g = 0; g < NT_ALL; g++) {
        if (g > 0) cp_wait<0>();          // W(g) resident (prefetched during g-1)
        const uint32_t wtile = sb + OFF_W + (uint32_t)(g & 1) * WTILE;
        const uint32_t aBase = wtile + (uint32_t)(wo * 32 * WPITCH) + aOff;

        #pragma unroll
        for (int b = 0; b < NB; b++) {    // compile-time b -> acc in regs
            const int i = g * 2 + b;
            __syncthreads();              // z(i) visible; z(i-1) readers done

            if (i + 1 < NITER && i != 63) build_z(i + 1);

            if (b == 0 && g + 1 < NT_ALL) {    // prefetch next W tile
                const unsigned char* src = g_Wpre + (size_t)(g + 1) * WTILE;
                uint32_t dst = sb + OFF_W + (uint32_t)((g + 1) & 1) * WTILE;
                #pragma unroll
                for (int r = 0; r < 5; r++) {
                    int idx = r * THREADS + tid;
                    if (idx < WTILE / 16)
                        cpa16(dst + (uint32_t)idx * 16, src + (size_t)idx * 16);
                }
                cp_commit();
            }

            // ---- MMA block for iter i (z buffer b): 4 k8 steps, single tf32 pass
            {
                const uint32_t zbuf  = sb + OFF_Z + (uint32_t)b * ZTILE;
                const uint32_t bBase = zbuf + (uint32_t)(wn * 32 * WPITCH) + bOff;
                #pragma unroll
                for (int ks = 0; ks < 4; ks++) {
                    uint32_t A0[4], A1[4], B01[4], B23[4];
                    const uint32_t ko = (uint32_t)(ks * 32);   // 8 tf32 k = 32B
                    ldmx4(A0, aBase + ko);
                    ldmx4(A1, aBase + 16 * WPITCH + ko);
                    ldmx4(B01, bBase + ko);
                    ldmx4(B23, bBase + 16 * WPITCH + ko);
                    mma_tf32(acc[b][0][0], A0, B01);     mma_tf32(acc[b][0][1], A0, B01 + 2);
                    mma_tf32(acc[b][0][2], A0, B23);     mma_tf32(acc[b][0][3], A0, B23 + 2);
                    mma_tf32(acc[b][1][0], A1, B01);     mma_tf32(acc[b][1][1], A1, B01 + 2);
                    mma_tf32(acc[b][1][2], A1, B23);     mma_tf32(acc[b][1][3], A1, B23 + 2);
                }
            }

            if (g == NT0 - 1 && b == 1) {
                // ======== layer-0 epilogue (i == 63) ========
                __syncthreads();                        // all iter-63 smem reads done
                float* ps = (float*)(smem + OFF_Z);     // overlay: 2*2*64 floats
                #pragma unroll
                for (int bb = 0; bb < NB; bb++) {
                    #pragma unroll
                    for (int mi = 0; mi < 2; mi++) {
                        int o  = wo * 32 + mi * 16 + lr;
                        float bias0 = b0g[o], bias1 = b0g[o + 8];
                        if (wo < 2) {
                            float* h0 = hs + (size_t)bb * (64 * HPAD) + o * HPAD;
                            float* h1 = h0 + 8 * HPAD;
                            #pragma unroll
                            for (int nj = 0; nj < 4; nj++) {
                                int dd = wn * 32 + nj * 8 + 2 * lc;
                                h0[dd]     = fmaxf(acc[bb][mi][nj][0] + bias0, 0.0f);
                                h0[dd + 1] = fmaxf(acc[bb][mi][nj][1] + bias0, 0.0f);
                                h1[dd]     = fmaxf(acc[bb][mi][nj][2] + bias1, 0.0f);
                                h1[dd + 1] = fmaxf(acc[bb][mi][nj][3] + bias1, 0.0f);
                            }
                        } else {
                            float s0 = 0.0f, s1 = 0.0f;
                            #pragma unroll
                            for (int nj = 0; nj < 4; nj++) {
                                s0 += fmaxf(acc[bb][mi][nj][0] + bias0, 0.0f)
                                    + fmaxf(acc[bb][mi][nj][1] + bias0, 0.0f);
                                s1 += fmaxf(acc[bb][mi][nj][2] + bias1, 0.0f)
                                    + fmaxf(acc[bb][mi][nj][3] + bias1, 0.0f);
                            }
                            s0 += __shfl_xor_sync(0xffffffffu, s0, 1);
                            s0 += __shfl_xor_sync(0xffffffffu, s0, 2);
                            s1 += __shfl_xor_sync(0xffffffffu, s1, 1);
                            s1 += __shfl_xor_sync(0xffffffffu, s1, 2);
                            if (lc == 0) {
                                int row = (wo - 2) * 32 + mi * 16 + lr;
                                ps[wn * 128 + bb * 64 + row]     = s0;
                                ps[wn * 128 + bb * 64 + row + 8] = s1;
                            }
                        }
                    }
                }
                __syncthreads();
                if (tid < 128) {
                    int bb = tid >> 6, row = tid & 63;
                    out[(size_t)(bbase + bb) * 192 + row] = ps[bb * 64 + row] + ps[128 + bb * 64 + row];
                }
                // reset accumulators for layer 1
                #pragma unroll
                for (int bb = 0; bb < NB; bb++)
                    #pragma unroll
                    for (int mi = 0; mi < 2; mi++)
                        #pragma unroll
                        for (int nj = 0; nj < 4; nj++)
                            #pragma unroll
                            for (int q = 0; q < 4; q++) acc[bb][mi][nj][q] = 0.0f;
                __syncthreads();      // ps reads done before z(64) overwrites buf0
                build_z(64);          // uses hs written above
            }
        }
    }

    // ======== layer-1 epilogue: out rows 64..191 ========
    __syncthreads();
    {
        float* ps = (float*)(smem + OFF_Z);   // 2*2*128 floats
        #pragma unroll
        for (int b = 0; b < NB; b++) {
            #pragma unroll
            for (int mi = 0; mi < 2; mi++) {
                int o = wo * 32 + mi * 16 + lr;
                float bias0 = b1g[o], bias1 = b1g[o + 8];
                float s0 = 0.0f, s1 = 0.0f;
                #pragma unroll
                for (int nj = 0; nj < 4; nj++) {
                    s0 += fmaxf(acc[b][mi][nj][0] + bias0, 0.0f)
                        + fmaxf(acc[b][mi][nj][1] + bias0, 0.0f);
                    s1 += fmaxf(acc[b][mi][nj][2] + bias1, 0.0f)
                        + fmaxf(acc[b][mi][nj][3] + bias1, 0.0f);
                }
                s0 += __shfl_xor_sync(0xffffffffu, s0, 1);
                s0 += __shfl_xor_sync(0xffffffffu, s0, 2);
                s1 += __shfl_xor_sync(0xffffffffu, s1, 1);
                s1 += __shfl_xor_sync(0xffffffffu, s1, 2);
                if (lc == 0) {
                    ps[wn * 256 + b * 128 + o]     = s0;
                    ps[wn * 256 + b * 128 + o + 8] = s1;
                }
            }
        }
        __syncthreads();
        {
            int b = tid >> 7, row = tid & 127;
            out[(size_t)(bbase + b) * 192 + 64 + row] = ps[tid] + ps[256 + tid];
        }
    }
}

// ---------------- launch ----------------
extern "C" void kernel_launch(void* const* d_in, const int* in_sizes, int n_in,
                              void* d_out, int out_size) {
    const float* xg = (const float*)d_in[0];   // (2048,32,64)
    const float* W0 = (const float*)d_in[1];   // (128,1024)
    const float* b0 = (const float*)d_in[2];   // (128)
    const float* W1 = (const float*)d_in[3];   // (128,2048)
    const float* b1 = (const float*)d_in[4];   // (128)
    float* out = (float*)d_out;                // (2048,192)

    prep_kernel<<<1536, 256>>>(W0, W1);

    cudaFuncSetAttribute((const void*)cin_mma_kernel,
                         cudaFuncAttributeMaxDynamicSharedMemorySize, SMEM_TOTAL);
    cin_mma_kernel<<<2048 / NB, THREADS, SMEM_TOTAL>>>(xg, b0, b1, out);
}

// round 9
// speedup vs baseline: 2.3506x; 1.1051x over previous
#include <cuda_runtime.h>
#include <cstdint>

// ---------------- configuration ----------------
#define THREADS 256
#define NT0     32           // layer-0 tiles (K=1024, 32 k each)
#define NT_ALL  96           // + 64 layer-1 tiles (K=2048)
#define WTILE   16384        // 128 rows x 128B, XOR-swizzled tf32
#define ZHALF   8192         // 64 rows x 128B per batch

// dynamic smem byte offsets (112KB per CTA -> 2 CTAs/SM)
#define OFF_X   0            // 2 * 8192   x fp32 [32][64] per batch
#define OFF_H   16384        // 2 * 16384  h fp32 [64][64] per batch
#define OFF_W   49152        // 2 * WTILE  (double-buffered W tile)
#define OFF_Z   81920        // 2 * (2*ZHALF) (double-buffered z, both batches)
#define SMEM_TOTAL 114688

// pre-converted, pre-swizzled W: 96 tf32 tiles
__device__ __align__(16) unsigned char g_Wpre[96 * WTILE];

// ---------------- helpers ----------------
static __device__ __forceinline__ uint32_t smem_u32(const void* p) {
    return (uint32_t)__cvta_generic_to_shared(p);
}
static __device__ __forceinline__ void cpa16(uint32_t dst, const void* src) {
    asm volatile("cp.async.cg.shared.global [%0], [%1], 16;" :: "r"(dst), "l"(src));
}
static __device__ __forceinline__ void cp_commit() { asm volatile("cp.async.commit_group;"); }
template <int N>
static __device__ __forceinline__ void cp_wait() { asm volatile("cp.async.wait_group %0;" :: "n"(N)); }

static __device__ __forceinline__ void sts128(uint32_t a, uint32_t r0, uint32_t r1, uint32_t r2, uint32_t r3) {
    asm volatile("st.shared.v4.b32 [%0], {%1, %2, %3, %4};" :: "r"(a), "r"(r0), "r"(r1), "r"(r2), "r"(r3));
}
static __device__ __forceinline__ void ldmx4(uint32_t* r, uint32_t a) {
    asm volatile("ldmatrix.sync.aligned.m8n8.x4.shared.b16 {%0,%1,%2,%3}, [%4];"
        : "=r"(r[0]), "=r"(r[1]), "=r"(r[2]), "=r"(r[3]) : "r"(a));
}
static __device__ __forceinline__ uint32_t f2tf32(float f) {
    uint32_t r; asm("cvt.rna.tf32.f32 %0, %1;" : "=r"(r) : "f"(f)); return r;
}
// m16n8k8 row.col tf32 -> f32, D += A*B (register-pure)
static __device__ __forceinline__ void mma_tf32(float* c, const uint32_t* a, const uint32_t* b) {
    asm("mma.sync.aligned.m16n8k8.row.col.f32.tf32.tf32.f32 "
        "{%0,%1,%2,%3}, {%4,%5,%6,%7}, {%8,%9}, {%0,%1,%2,%3};"
        : "+f"(c[0]), "+f"(c[1]), "+f"(c[2]), "+f"(c[3])
        : "r"(a[0]), "r"(a[1]), "r"(a[2]), "r"(a[3]), "r"(b[0]), "r"(b[1]));
}

// ---------------- prep: round W to tf32, XOR-swizzled 32-k tiles ----------------
__global__ void prep_kernel(const float* __restrict__ W0, const float* __restrict__ W1) {
    int idx = blockIdx.x * 256 + threadIdx.x;      // 0..393215
    float w; int o, k; size_t base;
    if (idx < 131072) { o = idx >> 10; k = idx & 1023; w = W0[idx]; base = (size_t)(k >> 5) * WTILE; }
    else { int j = idx - 131072; o = j >> 11; k = j & 2047; w = W1[j]; base = (size_t)(32 + (k >> 5)) * WTILE; }
    uint32_t c = (uint32_t)((k >> 2) & 7);         // 16B chunk within row
    size_t off = base + (size_t)o * 128 + (size_t)(((c ^ (o & 7)) << 4) + (k & 3) * 4);
    *(uint32_t*)(g_Wpre + off) = f2tf32(w);
}

// ---------------- main kernel ----------------
__global__ __launch_bounds__(THREADS, 2)
void cin_mma_kernel(const float* __restrict__ xg,
                    const float* __restrict__ b0g,
                    const float* __restrict__ b1g,
                    float* __restrict__ out)
{
    extern __shared__ __align__(256) unsigned char smem[];
    const uint32_t sb = smem_u32(smem);
    const int tid  = threadIdx.x;
    const int wid  = tid >> 5;
    const int lane = tid & 31;
    const int lr   = lane >> 2;
    const int lc   = lane & 3;

    const int bz = wid >> 2;        // warp's batch (0/1)
    const int wo = wid & 3;         // warp o-tile -> o base wo*32

    // swizzled ldmatrix addressing
    const uint32_t l7  = (uint32_t)(lane & 7);
    const uint32_t aHi = (uint32_t)((lane >> 4) & 1);
    const uint32_t bHi = (uint32_t)((lane >> 3) & 1);
    const uint32_t aRowOff = (uint32_t)((wo * 32 + (lane & 15)) * 128);
    const uint32_t bRowOff = (uint32_t)(((lane & 7) + ((lane & 16) >> 1)) * 128);

    float* xs = (float*)(smem + OFF_X);
    float* hs = (float*)(smem + OFF_H);

    const int bbase = blockIdx.x * 2;

    // initial loads: x (16KB) + W tile 0 (16KB), one group, 4+4 chunks/thread
    {
        const char* src = (const char*)(xg + (size_t)bbase * 2048);
        #pragma unroll
        for (int r = 0; r < 4; r++)
            cpa16(sb + OFF_X + (uint32_t)(r * THREADS + tid) * 16, src + (size_t)(r * THREADS + tid) * 16);
        #pragma unroll
        for (int r = 0; r < 4; r++)
            cpa16(sb + OFF_W + (uint32_t)(r * THREADS + tid) * 16, g_Wpre + (size_t)(r * THREADS + tid) * 16);
        cp_commit();
    }

    // z producer mapping: thread -> (batch bzt, d, m0..m0+15)
    const int d   = tid & 63;
    const int m0  = ((tid >> 6) & 1) * 16;
    const int bzt = tid >> 7;
    const uint32_t d7 = (uint32_t)(d & 7);
    const uint32_t m4 = (uint32_t)(m0 >> 2);

    cp_wait<0>();
    __syncthreads();

    // register-cached x values (loop-invariant for both layers)
    float xmc[16];
    #pragma unroll
    for (int j = 0; j < 16; j++) xmc[j] = xs[bzt * 2048 + (m0 + j) * 64 + d];

    // build z tile for tile j (both batches), buffer j&1. Never touches acc.
    auto build_z = [&](int j) {
        const uint32_t zb = sb + OFF_Z + (uint32_t)(j & 1) * (2 * ZHALF) + (uint32_t)bzt * ZHALF
                          + (uint32_t)(d * 128);
        const float xh = (j < NT0) ? xs[bzt * 2048 + j * 64 + d]
                                   : hs[bzt * 4096 + (j - NT0) * 64 + d];
        uint32_t t[16];
        #pragma unroll
        for (int jj = 0; jj < 16; jj++) t[jj] = f2tf32(xh * xmc[jj]);
        #pragma unroll
        for (int c4 = 0; c4 < 4; c4++)
            sts128(zb + (((m4 + (uint32_t)c4) ^ d7) << 4), t[4*c4], t[4*c4+1], t[4*c4+2], t[4*c4+3]);
    };

    float acc[2][8][4];             // [mi][nj][q] — statically indexed
    #pragma unroll
    for (int mi = 0; mi < 2; mi++)
        #pragma unroll
        for (int nj = 0; nj < 8; nj++)
            #pragma unroll
            for (int q = 0; q < 4; q++) acc[mi][nj][q] = 0.0f;

    build_z(0);

    for (int g = 0; g < NT_ALL; g++) {
        if (g > 0) cp_wait<0>();          // W(g) resident
        __syncthreads();                  // z(g) visible; z(g-1) readers done

        if (g + 1 < NT_ALL && g != NT0 - 1) build_z(g + 1);

        if (g + 1 < NT_ALL) {             // prefetch next W tile (4 chunks/thread)
            const unsigned char* src = g_Wpre + (size_t)(g + 1) * WTILE;
            uint32_t dst = sb + OFF_W + (uint32_t)((g + 1) & 1) * WTILE;
            #pragma unroll
            for (int r = 0; r < 4; r++)
                cpa16(dst + (uint32_t)(r * THREADS + tid) * 16, src + (size_t)(r * THREADS + tid) * 16);
            cp_commit();
        }

        // ---- MMA: warp = (batch bz, o-tile wo), all 64 d, 32 k
        {
            const uint32_t wbuf = sb + OFF_W + (uint32_t)(g & 1) * WTILE;
            const uint32_t aA0  = wbuf + aRowOff;           // rows wo*32 .. +15
            const uint32_t aA1  = aA0 + 16 * 128;           // rows +16 .. +31
            const uint32_t bB   = sb + OFF_Z + (uint32_t)(g & 1) * (2 * ZHALF)
                                + (uint32_t)bz * ZHALF + bRowOff;
            #pragma unroll
            for (uint32_t ks = 0; ks < 4; ks++) {
                uint32_t A0[4], A1[4], B0[4], B1[4], B2[4], B3[4];
                const uint32_t swA = (((ks << 1) | aHi) ^ l7) << 4;
                const uint32_t swB = (((ks << 1) | bHi) ^ l7) << 4;
                ldmx4(A0, aA0 + swA);
                ldmx4(A1, aA1 + swA);
                ldmx4(B0, bB + swB);
                ldmx4(B1, bB + 2048 + swB);
                ldmx4(B2, bB + 4096 + swB);
                ldmx4(B3, bB + 6144 + swB);
                mma_tf32(acc[0][0], A0, B0);  mma_tf32(acc[0][1], A0, B0 + 2);
                mma_tf32(acc[0][2], A0, B1);  mma_tf32(acc[0][3], A0, B1 + 2);
                mma_tf32(acc[0][4], A0, B2);  mma_tf32(acc[0][5], A0, B2 + 2);
                mma_tf32(acc[0][6], A0, B3);  mma_tf32(acc[0][7], A0, B3 + 2);
                mma_tf32(acc[1][0], A1, B0);  mma_tf32(acc[1][1], A1, B0 + 2);
                mma_tf32(acc[1][2], A1, B1);  mma_tf32(acc[1][3], A1, B1 + 2);
                mma_tf32(acc[1][4], A1, B2);  mma_tf32(acc[1][5], A1, B2 + 2);
                mma_tf32(acc[1][6], A1, B3);  mma_tf32(acc[1][7], A1, B3 + 2);
            }
        }

        if (g == NT0 - 1) {
            // ======== layer-0 epilogue ========
            __syncthreads();              // all layer-0 MMA smem reads done
            #pragma unroll
            for (int mi = 0; mi < 2; mi++) {
                const int o = wo * 32 + mi * 16 + lr;
                const float bias0 = b0g[o], bias1 = b0g[o + 8];
                if (wo < 2) {             // rows 0..63 -> h
                    float* h0 = hs + bz * 4096 + o * 64;
                    float* h1 = h0 + 8 * 64;
                    #pragma unroll
                    for (int nj = 0; nj < 8; nj++) {
                        const int dd = nj * 8 + 2 * lc;
                        h0[dd]     = fmaxf(acc[mi][nj][0] + bias0, 0.0f);
                        h0[dd + 1] = fmaxf(acc[mi][nj][1] + bias0, 0.0f);
                        h1[dd]     = fmaxf(acc[mi][nj][2] + bias1, 0.0f);
                        h1[dd + 1] = fmaxf(acc[mi][nj][3] + bias1, 0.0f);
                    }
                } else {                  // rows 64..127 -> out rows 0..63
                    float s0 = 0.0f, s1 = 0.0f;
                    #pragma unroll
                    for (int nj = 0; nj < 8; nj++) {
                        s0 += fmaxf(acc[mi][nj][0] + bias0, 0.0f)
                            + fmaxf(acc[mi][nj][1] + bias0, 0.0f);
                        s1 += fmaxf(acc[mi][nj][2] + bias1, 0.0f)
                            + fmaxf(acc[mi][nj][3] + bias1, 0.0f);
                    }
                    s0 += __shfl_xor_sync(0xffffffffu, s0, 1);
                    s0 += __shfl_xor_sync(0xffffffffu, s0, 2);
                    s1 += __shfl_xor_sync(0xffffffffu, s1, 1);
                    s1 += __shfl_xor_sync(0xffffffffu, s1, 2);
                    if (lc == 0) {
                        out[(size_t)(bbase + bz) * 192 + (o - 64)]     = s0;
                        out[(size_t)(bbase + bz) * 192 + (o - 64) + 8] = s1;
                    }
                }
            }
            #pragma unroll
            for (int mi = 0; mi < 2; mi++)
                #pragma unroll
                for (int nj = 0; nj < 8; nj++)
                    #pragma unroll
                    for (int q = 0; q < 4; q++) acc[mi][nj][q] = 0.0f;
            __syncthreads();              // h complete before z(32) reads it
            build_z(NT0);                 // into buf 0 (last read by MMA(30))
        }
    }

    // ======== layer-1 epilogue: out rows 64..191, direct ========
    #pragma unroll
    for (int mi = 0; mi < 2; mi++) {
        const int o = wo * 32 + mi * 16 + lr;
        const float bias0 = b1g[o], bias1 = b1g[o + 8];
        float s0 = 0.0f, s1 = 0.0f;
        #pragma unroll
        for (int nj = 0; nj < 8; nj++) {
            s0 += fmaxf(acc[mi][nj][0] + bias0, 0.0f)
                + fmaxf(acc[mi][nj][1] + bias0, 0.0f);
            s1 += fmaxf(acc[mi][nj][2] + bias1, 0.0f)
                + fmaxf(acc[mi][nj][3] + bias1, 0.0f);
        }
        s0 += __shfl_xor_sync(0xffffffffu, s0, 1);
        s0 += __shfl_xor_sync(0xffffffffu, s0, 2);
        s1 += __shfl_xor_sync(0xffffffffu, s1, 1);
        s1 += __shfl_xor_sync(0xffffffffu, s1, 2);
        if (lc == 0) {
            out[(size_t)(bbase + bz) * 192 + 64 + o]     = s0;
            out[(size_t)(bbase + bz) * 192 + 64 + o + 8] = s1;
        }
    }
}

// ---------------- launch ----------------
extern "C" void kernel_launch(void* const* d_in, const int* in_sizes, int n_in,
                              void* d_out, int out_size) {
    const float* xg = (const float*)d_in[0];   // (2048,32,64)
    const float* W0 = (const float*)d_in[1];   // (128,1024)
    const float* b0 = (const float*)d_in[2];   // (128)
    const float* W1 = (const float*)d_in[3];   // (128,2048)
    const float* b1 = (const float*)d_in[4];   // (128)
    float* out = (float*)d_out;                // (2048,192)

    prep_kernel<<<1536, 256>>>(W0, W1);

    cudaFuncSetAttribute((const void*)cin_mma_kernel,
                         cudaFuncAttributeMaxDynamicSharedMemorySize, SMEM_TOTAL);
    cin_mma_kernel<<<1024, THREADS, SMEM_TOTAL>>>(xg, b0, b1, out);
}

// round 10
// speedup vs baseline: 2.5454x; 1.0829x over previous
#include <cuda_runtime.h>
#include <cstdint>

// ---------------- configuration ----------------
#define THREADS 128
#define NT0     32           // layer-0 tiles (K=1024, 32 k each)
#define NT_ALL  96           // + 64 layer-1 tiles (K=2048)
#define WTILE   16384        // 128 rows x 128B, XOR-swizzled tf32
#define ZHALF   8192         // 64 rows x 128B per batch

// dynamic smem byte offsets (112KB per CTA -> 2 CTAs/SM)
#define OFF_X   0            // 2 * 8192   x fp32 [32][64] per batch
#define OFF_H   16384        // 2 * 16384  h fp32 [64][64] per batch
#define OFF_W   49152        // 2 * WTILE  (double-buffered W tile)
#define OFF_Z   81920        // 2 * (2*ZHALF) (double-buffered z, both batches)
#define SMEM_TOTAL 114688

// pre-converted, pre-swizzled W: 96 tf32 tiles
__device__ __align__(16) unsigned char g_Wpre[96 * WTILE];

// ---------------- helpers ----------------
static __device__ __forceinline__ uint32_t smem_u32(const void* p) {
    return (uint32_t)__cvta_generic_to_shared(p);
}
static __device__ __forceinline__ void cpa16(uint32_t dst, const void* src) {
    asm volatile("cp.async.cg.shared.global [%0], [%1], 16;" :: "r"(dst), "l"(src));
}
static __device__ __forceinline__ void cp_commit() { asm volatile("cp.async.commit_group;"); }
template <int N>
static __device__ __forceinline__ void cp_wait() { asm volatile("cp.async.wait_group %0;" :: "n"(N)); }

static __device__ __forceinline__ void sts128(uint32_t a, uint32_t r0, uint32_t r1, uint32_t r2, uint32_t r3) {
    asm volatile("st.shared.v4.b32 [%0], {%1, %2, %3, %4};" :: "r"(a), "r"(r0), "r"(r1), "r"(r2), "r"(r3));
}
static __device__ __forceinline__ void ldmx4(uint32_t* r, uint32_t a) {
    asm volatile("ldmatrix.sync.aligned.m8n8.x4.shared.b16 {%0,%1,%2,%3}, [%4];"
        : "=r"(r[0]), "=r"(r[1]), "=r"(r[2]), "=r"(r[3]) : "r"(a));
}
static __device__ __forceinline__ uint32_t f2tf32(float f) {
    uint32_t r; asm("cvt.rna.tf32.f32 %0, %1;" : "=r"(r) : "f"(f)); return r;
}
// m16n8k8 row.col tf32 -> f32, D += A*B (register-pure)
static __device__ __forceinline__ void mma_tf32(float* c, const uint32_t* a, const uint32_t* b) {
    asm("mma.sync.aligned.m16n8k8.row.col.f32.tf32.tf32.f32 "
        "{%0,%1,%2,%3}, {%4,%5,%6,%7}, {%8,%9}, {%0,%1,%2,%3};"
        : "+f"(c[0]), "+f"(c[1]), "+f"(c[2]), "+f"(c[3])
        : "r"(a[0]), "r"(a[1]), "r"(a[2]), "r"(a[3]), "r"(b[0]), "r"(b[1]));
}

// ---------------- prep: round W to tf32, XOR-swizzled 32-k tiles ----------------
__global__ void prep_kernel(const float* __restrict__ W0, const float* __restrict__ W1) {
    int idx = blockIdx.x * 256 + threadIdx.x;      // 0..393215
    float w; int o, k; size_t base;
    if (idx < 131072) { o = idx >> 10; k = idx & 1023; w = W0[idx]; base = (size_t)(k >> 5) * WTILE; }
    else { int j = idx - 131072; o = j >> 11; k = j & 2047; w = W1[j]; base = (size_t)(32 + (k >> 5)) * WTILE; }
    uint32_t c = (uint32_t)((k >> 2) & 7);         // 16B chunk within row
    size_t off = base + (size_t)o * 128 + (size_t)(((c ^ (o & 7)) << 4) + (k & 3) * 4);
    *(uint32_t*)(g_Wpre + off) = f2tf32(w);
}

// ---------------- main kernel ----------------
__global__ __launch_bounds__(THREADS, 2)
void cin_mma_kernel(const float* __restrict__ xg,
                    const float* __restrict__ b0g,
                    const float* __restrict__ b1g,
                    float* __restrict__ out)
{
    extern __shared__ __align__(256) unsigned char smem[];
    const uint32_t sb = smem_u32(smem);
    const int tid  = threadIdx.x;
    const int wid  = tid >> 5;
    const int lane = tid & 31;
    const int lr   = lane >> 2;
    const int lc   = lane & 3;

    const int bz = wid >> 1;        // warp's batch (0/1)
    const int oh = wid & 1;         // warp o-half -> o base oh*64

    // swizzled ldmatrix addressing
    const uint32_t l7  = (uint32_t)(lane & 7);
    const uint32_t aHi = (uint32_t)((lane >> 4) & 1);
    const uint32_t bHi = (uint32_t)((lane >> 3) & 1);
    const uint32_t aRowOff = (uint32_t)((oh * 64 + (lane & 15)) * 128);
    const uint32_t bRowOff = (uint32_t)(((lane & 7) + ((lane & 16) >> 1)) * 128);

    float* xs = (float*)(smem + OFF_X);
    float* hs = (float*)(smem + OFF_H);

    const int bbase = blockIdx.x * 2;

    // initial loads: x (16KB) + W tile 0 (16KB), 8+8 chunks/thread
    {
        const char* src = (const char*)(xg + (size_t)bbase * 2048);
        #pragma unroll
        for (int r = 0; r < 8; r++)
            cpa16(sb + OFF_X + (uint32_t)(r * THREADS + tid) * 16, src + (size_t)(r * THREADS + tid) * 16);
        #pragma unroll
        for (int r = 0; r < 8; r++)
            cpa16(sb + OFF_W + (uint32_t)(r * THREADS + tid) * 16, g_Wpre + (size_t)(r * THREADS + tid) * 16);
        cp_commit();
    }

    // z producer mapping: thread -> (batch bzt, d), all 32 m
    const int d   = tid & 63;
    const int bzt = tid >> 6;
    const uint32_t d7 = (uint32_t)(d & 7);

    cp_wait<0>();
    __syncthreads();

    // register-cached x values (loop-invariant across both layers)
    float xmc[32];
    #pragma unroll
    for (int j = 0; j < 32; j++) xmc[j] = xs[bzt * 2048 + j * 64 + d];

    // build z tile for tile j (both batches), buffer j&1. Never touches acc.
    auto build_z = [&](int j) {
        const uint32_t zb = sb + OFF_Z + (uint32_t)(j & 1) * (2 * ZHALF) + (uint32_t)bzt * ZHALF
                          + (uint32_t)(d * 128);
        const float xh = (j < NT0) ? xs[bzt * 2048 + j * 64 + d]
                                   : hs[bzt * 4096 + (j - NT0) * 64 + d];
        uint32_t t[32];
        #pragma unroll
        for (int jj = 0; jj < 32; jj++) t[jj] = f2tf32(xh * xmc[jj]);
        #pragma unroll
        for (int c4 = 0; c4 < 8; c4++)
            sts128(zb + (((uint32_t)c4 ^ d7) << 4), t[4*c4], t[4*c4+1], t[4*c4+2], t[4*c4+3]);
    };

    float acc[4][8][4];             // [mi][nj][q] — statically indexed, 128 regs
    #pragma unroll
    for (int mi = 0; mi < 4; mi++)
        #pragma unroll
        for (int nj = 0; nj < 8; nj++)
            #pragma unroll
            for (int q = 0; q < 4; q++) acc[mi][nj][q] = 0.0f;

    build_z(0);

    for (int g = 0; g < NT_ALL; g++) {
        if (g > 0) cp_wait<0>();          // W(g) resident
        __syncthreads();                  // z(g) visible; z(g-1) readers done

        if (g + 1 < NT_ALL && g != NT0 - 1) build_z(g + 1);

        if (g + 1 < NT_ALL) {             // prefetch next W tile (8 chunks/thread)
            const unsigned char* src = g_Wpre + (size_t)(g + 1) * WTILE;
            uint32_t dst = sb + OFF_W + (uint32_t)((g + 1) & 1) * WTILE;
            #pragma unroll
            for (int r = 0; r < 8; r++)
                cpa16(dst + (uint32_t)(r * THREADS + tid) * 16, src + (size_t)(r * THREADS + tid) * 16);
            cp_commit();
        }

        // ---- MMA: warp = (batch bz, o-half oh): 64 o x 64 d x 32 k
        {
            const uint32_t wbuf = sb + OFF_W + (uint32_t)(g & 1) * WTILE;
            const uint32_t aA   = wbuf + aRowOff;
            const uint32_t bB   = sb + OFF_Z + (uint32_t)(g & 1) * (2 * ZHALF)
                                + (uint32_t)bz * ZHALF + bRowOff;
            #pragma unroll
            for (uint32_t ks = 0; ks < 4; ks++) {
                uint32_t A[4][4], B[4][4];
                const uint32_t swA = (((ks << 1) | aHi) ^ l7) << 4;
                const uint32_t swB = (((ks << 1) | bHi) ^ l7) << 4;
                #pragma unroll
                for (int t4 = 0; t4 < 4; t4++) ldmx4(A[t4], aA + (uint32_t)(t4 * 16 * 128) + swA);
                #pragma unroll
                for (int t4 = 0; t4 < 4; t4++) ldmx4(B[t4], bB + (uint32_t)(t4 * 2048) + swB);
                #pragma unroll
                for (int mi = 0; mi < 4; mi++)
                    #pragma unroll
                    for (int t4 = 0; t4 < 4; t4++) {
                        mma_tf32(acc[mi][2*t4],     A[mi], B[t4]);
                        mma_tf32(acc[mi][2*t4 + 1], A[mi], B[t4] + 2);
                    }
            }
        }

        if (g == NT0 - 1) {
            // ======== layer-0 epilogue ========
            __syncthreads();              // all layer-0 MMA smem reads done
            #pragma unroll
            for (int mi = 0; mi < 4; mi++) {
                const int o = oh * 64 + mi * 16 + lr;
                const float bias0 = b0g[o], bias1 = b0g[o + 8];
                if (oh == 0) {            // rows 0..63 -> h
                    float* h0 = hs + bz * 4096 + o * 64;
                    float* h1 = h0 + 8 * 64;
                    #pragma unroll
                    for (int nj = 0; nj < 8; nj++) {
                        const int dd = nj * 8 + 2 * lc;
                        h0[dd]     = fmaxf(acc[mi][nj][0] + bias0, 0.0f);
                        h0[dd + 1] = fmaxf(acc[mi][nj][1] + bias0, 0.0f);
                        h1[dd]     = fmaxf(acc[mi][nj][2] + bias1, 0.0f);
                        h1[dd + 1] = fmaxf(acc[mi][nj][3] + bias1, 0.0f);
                    }
                } else {                  // rows 64..127 -> out rows 0..63
                    float s0 = 0.0f, s1 = 0.0f;
                    #pragma unroll
                    for (int nj = 0; nj < 8; nj++) {
                        s0 += fmaxf(acc[mi][nj][0] + bias0, 0.0f)
                            + fmaxf(acc[mi][nj][1] + bias0, 0.0f);
                        s1 += fmaxf(acc[mi][nj][2] + bias1, 0.0f)
                            + fmaxf(acc[mi][nj][3] + bias1, 0.0f);
                    }
                    s0 += __shfl_xor_sync(0xffffffffu, s0, 1);
                    s0 += __shfl_xor_sync(0xffffffffu, s0, 2);
                    s1 += __shfl_xor_sync(0xffffffffu, s1, 1);
                    s1 += __shfl_xor_sync(0xffffffffu, s1, 2);
                    if (lc == 0) {
                        out[(size_t)(bbase + bz) * 192 + (o - 64)]     = s0;
                        out[(size_t)(bbase + bz) * 192 + (o - 64) + 8] = s1;
                    }
                }
            }
            #pragma unroll
            for (int mi = 0; mi < 4; mi++)
                #pragma unroll
                for (int nj = 0; nj < 8; nj++)
                    #pragma unroll
                    for (int q = 0; q < 4; q++) acc[mi][nj][q] = 0.0f;
            __syncthreads();              // h complete before z(32) reads it
            build_z(NT0);                 // into buf 0 (last read by MMA(30))
        }
    }

    // ======== layer-1 epilogue: out rows 64..191, direct ========
    #pragma unroll
    for (int mi = 0; mi < 4; mi++) {
        const int o = oh * 64 + mi * 16 + lr;
        const float bias0 = b1g[o], bias1 = b1g[o + 8];
        float s0 = 0.0f, s1 = 0.0f;
        #pragma unroll
        for (int nj = 0; nj < 8; nj++) {
            s0 += fmaxf(acc[mi][nj][0] + bias0, 0.0f)
                + fmaxf(acc[mi][nj][1] + bias0, 0.0f);
            s1 += fmaxf(acc[mi][nj][2] + bias1, 0.0f)
                + fmaxf(acc[mi][nj][3] + bias1, 0.0f);
        }
        s0 += __shfl_xor_sync(0xffffffffu, s0, 1);
        s0 += __shfl_xor_sync(0xffffffffu, s0, 2);
        s1 += __shfl_xor_sync(0xffffffffu, s1, 1);
        s1 += __shfl_xor_sync(0xffffffffu, s1, 2);
        if (lc == 0) {
            out[(size_t)(bbase + bz) * 192 + 64 + o]     = s0;
            out[(size_t)(bbase + bz) * 192 + 64 + o + 8] = s1;
        }
    }
}

// ---------------- launch ----------------
extern "C" void kernel_launch(void* const* d_in, const int* in_sizes, int n_in,
                              void* d_out, int out_size) {
    const float* xg = (const float*)d_in[0];   // (2048,32,64)
    const float* W0 = (const float*)d_in[1];   // (128,1024)
    const float* b0 = (const float*)d_in[2];   // (128)
    const float* W1 = (const float*)d_in[3];   // (128,2048)
    const float* b1 = (const float*)d_in[4];   // (128)
    float* out = (float*)d_out;                // (2048,192)

    prep_kernel<<<1536, 256>>>(W0, W1);

    cudaFuncSetAttribute((const void*)cin_mma_kernel,
                         cudaFuncAttributeMaxDynamicSharedMemorySize, SMEM_TOTAL);
    cin_mma_kernel<<<1024, THREADS, SMEM_TOTAL>>>(xg, b0, b1, out);
}